// round 2
// baseline (speedup 1.0000x reference)
#include <cuda_runtime.h>
#include <math.h>

// Problem shape (fixed per reference): x [32, 512, 2048] f32, codebook [1024, 512] f32.
// out = gathered codebook rows laid out back as [N, C, T], plus two scalar zeros.
#define NB 32
#define CD 512
#define TD 2048
#define KC 1024
#define NT_ROWS (NB * TD)          // 65536 (n,t) rows
#define XD_ELEMS ((long long)NB * CD * TD)

// Scratch (no cudaMalloc allowed): per-row winning code index + half codebook norms.
__device__ int   g_code_idx[NT_ROWS];
__device__ float g_half_cnorm[KC];

// ---------------------------------------------------------------------------
// Kernel 1: half squared norms of each codebook row. 1024 blocks x 128 threads.
// ---------------------------------------------------------------------------
__global__ void vq_cnorm_kernel(const float* __restrict__ cb)
{
    const int k   = blockIdx.x;
    const int tid = threadIdx.x;                       // 128 threads, 4 floats each
    const float4 v = reinterpret_cast<const float4*>(cb + (size_t)k * CD)[tid];
    float s = v.x * v.x + v.y * v.y + v.z * v.z + v.w * v.w;
#pragma unroll
    for (int o = 16; o > 0; o >>= 1) s += __shfl_xor_sync(0xffffffffu, s, o);
    __shared__ float ws[4];
    if ((tid & 31) == 0) ws[tid >> 5] = s;
    __syncthreads();
    if (tid == 0) g_half_cnorm[k] = 0.5f * (ws[0] + ws[1] + ws[2] + ws[3]);
}

// ---------------------------------------------------------------------------
// Kernel 2: fused GEMM + argmax(dot - 0.5*||c||^2)  ==  argmin distance.
// Block = 128 rows (consecutive t within one n) x all 1024 codes (8 tiles of 128).
// Inner GEMM tile: 128x128x8, 256 threads, 8x8 micro-tile, smem double-buffered.
// x is [N, C, T] so a row-tile of 128 consecutive t gives perfectly coalesced
// loads of Xs[cc][tt] (the "transpose" is free).
// ---------------------------------------------------------------------------
__global__ __launch_bounds__(256) void vq_argmin_kernel(
    const float* __restrict__ x, const float* __restrict__ cb)
{
    __shared__ float Xs[2][8][128];
    __shared__ float Cs[2][8][128];
    __shared__ float s_rv[128][17];   // padded: 16-entry cross-thread reduce per row
    __shared__ int   s_ri[128][17];

    const int tid = threadIdx.x;
    const int r0  = blockIdx.x * 128;          // first (n,t) row of this block
    const int n   = r0 >> 11;                  // / 2048
    const int t0  = r0 & (TD - 1);
    const float* xbase = x + (size_t)n * CD * TD + t0;

    const int tx = tid & 15;                   // code group   (8 codes each)
    const int ty = tid >> 4;                   // row group    (8 rows each)

    // gmem staging assignments (one float4 per thread per chunk)
    const int x_cc = tid >> 5;                 // 0..7  (c within chunk)
    const int x_t4 = (tid & 31) << 2;          // 0..124 (t, x4)
    const int c_kk = tid >> 1;                 // 0..127 (code)
    const int c_c4 = (tid & 1) << 2;           // 0 or 4 (c within chunk, x4)

    float bestv[8];
    int   besti[8];
#pragma unroll
    for (int i = 0; i < 8; ++i) { bestv[i] = -INFINITY; besti[i] = 0; }

    for (int kt = 0; kt < 8; ++kt) {           // 8 code tiles of 128
        const int k0 = kt << 7;

        float acc[8][8];
#pragma unroll
        for (int i = 0; i < 8; ++i)
#pragma unroll
            for (int j = 0; j < 8; ++j) acc[i][j] = 0.0f;

        // prefetch chunk 0 of the C-dimension
        float4 xa = *reinterpret_cast<const float4*>(xbase + (size_t)x_cc * TD + x_t4);
        float4 ca = *reinterpret_cast<const float4*>(cb + (size_t)(k0 + c_kk) * CD + c_c4);
        __syncthreads();                       // previous tile's readers done
        *reinterpret_cast<float4*>(&Xs[0][x_cc][x_t4]) = xa;
        Cs[0][c_c4 + 0][c_kk] = ca.x;
        Cs[0][c_c4 + 1][c_kk] = ca.y;
        Cs[0][c_c4 + 2][c_kk] = ca.z;
        Cs[0][c_c4 + 3][c_kk] = ca.w;
        __syncthreads();

        for (int kc = 0; kc < 64; ++kc) {      // 512 / 8 chunks over C
            const int cur = kc & 1;
            if (kc < 63) {                     // prefetch next chunk into registers
                const int cb0 = (kc + 1) << 3;
                xa = *reinterpret_cast<const float4*>(
                    xbase + (size_t)(cb0 + x_cc) * TD + x_t4);
                ca = *reinterpret_cast<const float4*>(
                    cb + (size_t)(k0 + c_kk) * CD + cb0 + c_c4);
            }
#pragma unroll
            for (int cc = 0; cc < 8; ++cc) {
                float xf[8], cf[8];
                *reinterpret_cast<float4*>(&xf[0]) =
                    *reinterpret_cast<const float4*>(&Xs[cur][cc][ty * 8]);
                *reinterpret_cast<float4*>(&xf[4]) =
                    *reinterpret_cast<const float4*>(&Xs[cur][cc][ty * 8 + 4]);
                *reinterpret_cast<float4*>(&cf[0]) =
                    *reinterpret_cast<const float4*>(&Cs[cur][cc][tx * 8]);
                *reinterpret_cast<float4*>(&cf[4]) =
                    *reinterpret_cast<const float4*>(&Cs[cur][cc][tx * 8 + 4]);
#pragma unroll
                for (int i = 0; i < 8; ++i)
#pragma unroll
                    for (int j = 0; j < 8; ++j)
                        acc[i][j] = fmaf(xf[i], cf[j], acc[i][j]);
            }
            if (kc < 63) {
                const int nxt = cur ^ 1;
                *reinterpret_cast<float4*>(&Xs[nxt][x_cc][x_t4]) = xa;
                Cs[nxt][c_c4 + 0][c_kk] = ca.x;
                Cs[nxt][c_c4 + 1][c_kk] = ca.y;
                Cs[nxt][c_c4 + 2][c_kk] = ca.z;
                Cs[nxt][c_c4 + 3][c_kk] = ca.w;
                __syncthreads();
            }
        }

        // fold this code tile into the per-row running best.
        // Ascending k with strict '>' keeps the LOWEST index on ties
        // (matches jnp.argmin first-occurrence semantics).
#pragma unroll
        for (int j = 0; j < 8; ++j) {
            const int   k = k0 + tx * 8 + j;
            const float h = __ldg(&g_half_cnorm[k]);
#pragma unroll
            for (int i = 0; i < 8; ++i) {
                const float v = acc[i][j] - h;   // dot - 0.5||c||^2 ; maximize
                if (v > bestv[i]) { bestv[i] = v; besti[i] = k; }
            }
        }
    }

    // cross-thread (16-way over tx) argmax reduce per row
#pragma unroll
    for (int i = 0; i < 8; ++i) {
        s_rv[ty * 8 + i][tx] = bestv[i];
        s_ri[ty * 8 + i][tx] = besti[i];
    }
    __syncthreads();
    if (tid < 128) {
        float bv = s_rv[tid][0];
        int   bi = s_ri[tid][0];
#pragma unroll
        for (int j = 1; j < 16; ++j) {
            const float v = s_rv[tid][j];
            const int   k = s_ri[tid][j];
            if (v > bv || (v == bv && k < bi)) { bv = v; bi = k; }
        }
        g_code_idx[r0 + tid] = bi;
    }
}

// ---------------------------------------------------------------------------
// Kernel 3: gather codebook rows back into [N, C, T] layout (+ scalar zeros).
// Thread = one (n,t): stores along t are fully coalesced; codebook (2 MB) is
// L2-resident so the per-lane scattered reads stay on-chip.
// ---------------------------------------------------------------------------
__global__ void vq_gather_kernel(const float* __restrict__ cb,
                                 float* __restrict__ out, long long out_size)
{
    const int r   = blockIdx.x * 256 + threadIdx.x;   // global (n,t) row
    const int n   = r >> 11;
    const int t   = r & (TD - 1);
    const int idx = g_code_idx[r];
    const float4* crow = reinterpret_cast<const float4*>(cb + (size_t)idx * CD);
    float* obase = out + (size_t)n * CD * TD + t;
#pragma unroll 4
    for (int c4 = 0; c4 < CD / 4; ++c4) {
        const float4 v = __ldg(crow + c4);
        obase[(size_t)(c4 * 4 + 0) * TD] = v.x;
        obase[(size_t)(c4 * 4 + 1) * TD] = v.y;
        obase[(size_t)(c4 * 4 + 2) * TD] = v.z;
        obase[(size_t)(c4 * 4 + 3) * TD] = v.w;
    }
    if (r == 0) {  // commit_loss, perplexity = 0.0 (if the harness appends them)
        for (long long e = XD_ELEMS; e < out_size; ++e) out[e] = 0.0f;
    }
}

// ---------------------------------------------------------------------------
extern "C" void kernel_launch(void* const* d_in, const int* in_sizes, int n_in,
                              void* d_out, int out_size)
{
    const float* x  = (const float*)d_in[0];
    const float* cb = (const float*)d_in[1];
    // defensive: identify operands by size (x has 33.5M elems, codebook 0.5M)
    if (n_in >= 2 && in_sizes[0] < in_sizes[1]) {
        const float* tmp = x; x = cb; cb = tmp;
    }
    float* out = (float*)d_out;

    vq_cnorm_kernel<<<KC, 128>>>(cb);
    vq_argmin_kernel<<<NT_ROWS / 128, 256>>>(x, cb);
    vq_gather_kernel<<<NT_ROWS / 256, 256>>>(cb, out, (long long)out_size);
}

// round 4
// speedup vs baseline: 2.0822x; 2.0822x over previous
#include <cuda_runtime.h>
#include <cuda_bf16.h>
#include <stdint.h>
#include <math.h>

// Shapes (fixed): x [32, 512, 2048] f32, codebook [1024, 512] f32.
#define NB 32
#define CD 512
#define TD 2048
#define KC 1024
#define NT_ROWS (NB * TD)
#define XD_ELEMS ((long long)NB * CD * TD)

#define ROWS_PER_CTA 128
#define N_SCREEN_CTAS (NT_ROWS / ROWS_PER_CTA)   // 512

// smem layout (bytes) for screen kernel
#define A_STRIDE_W 260            // (512+8) bf16 per row = 260 words, pad kills conflicts
#define SM_AS 0                                   // 128*520*2 = 133120
#define SM_BS 133120                              // B chunk: 128 codes * 72 bf16 = 18432
#define B_STRIDE_W 36             // (64+8) bf16 = 36 words
#define SM_TV 151552                              // top-4 vals: 32*256*4 = 32768
#define SM_TI (151552 + 32768)                    // top-4 idx : 32768
#define SM_TOTAL (SM_TI + 32768)                  // 217088
// merge region reuses SM_BS (needs 16KB, has 18KB)
#define SM_MV SM_BS
#define SM_MI (SM_BS + 8192)

// ---- global scratch (no cudaMalloc allowed) ----
__device__ __align__(16) __nv_bfloat16 g_cb_bf16[KC * CD];   // 1 MB
__device__ float g_half_hat[KC];      // 0.5*||bf16(c)||^2 (screen-consistent)
__device__ float g_half_exact[KC];    // 0.5*||c||^2 fp32 (rescore)
__device__ __align__(16) float g_scr_v[NT_ROWS * 4];
__device__ __align__(16) int   g_scr_i[NT_ROWS * 4];

// ===========================================================================
// Kernel 1: codebook prep — bf16 convert + half norms (exact f32 & bf16-hat).
// ===========================================================================
__global__ void vq_prep_kernel(const float* __restrict__ cb)
{
    const int k = blockIdx.x;
    const int tid = threadIdx.x;                    // 128 threads x float4
    const float4 v = reinterpret_cast<const float4*>(cb + (size_t)k * CD)[tid];

    __nv_bfloat162 p01 = __floats2bfloat162_rn(v.x, v.y);
    __nv_bfloat162 p23 = __floats2bfloat162_rn(v.z, v.w);
    uint2 u;
    u.x = *reinterpret_cast<uint32_t*>(&p01);
    u.y = *reinterpret_cast<uint32_t*>(&p23);
    reinterpret_cast<uint2*>(g_cb_bf16)[(size_t)k * (CD / 4) + tid] = u;

    float se = v.x * v.x + v.y * v.y + v.z * v.z + v.w * v.w;
    const float h0 = __bfloat162float(p01.x), h1 = __bfloat162float(p01.y);
    const float h2 = __bfloat162float(p23.x), h3 = __bfloat162float(p23.y);
    float sh = h0 * h0 + h1 * h1 + h2 * h2 + h3 * h3;
#pragma unroll
    for (int o = 16; o > 0; o >>= 1) {
        se += __shfl_xor_sync(0xffffffffu, se, o);
        sh += __shfl_xor_sync(0xffffffffu, sh, o);
    }
    __shared__ float wse[4], wsh[4];
    if ((tid & 31) == 0) { wse[tid >> 5] = se; wsh[tid >> 5] = sh; }
    __syncthreads();
    if (tid == 0) {
        g_half_exact[k] = 0.5f * (wse[0] + wse[1] + wse[2] + wse[3]);
        g_half_hat[k]   = 0.5f * (wsh[0] + wsh[1] + wsh[2] + wsh[3]);
    }
}

// ---------------------------------------------------------------------------
__device__ __forceinline__ void mma16816(float* d, const uint32_t* a,
                                         const uint32_t* b)
{
    asm volatile(
        "mma.sync.aligned.m16n8k16.row.col.f32.bf16.bf16.f32 "
        "{%0,%1,%2,%3}, {%4,%5,%6,%7}, {%8,%9}, {%0,%1,%2,%3};"
        : "+f"(d[0]), "+f"(d[1]), "+f"(d[2]), "+f"(d[3])
        : "r"(a[0]), "r"(a[1]), "r"(a[2]), "r"(a[3]), "r"(b[0]), "r"(b[1]));
}

// sorted-desc insert into a 4-entry smem-resident list (layout [slot*4+j][256])
__device__ __forceinline__ void ins4(float* tvs, int* tis, int tid, int slot,
                                     float v, int idx)
{
    const int b = (slot << 2) * 256 + tid;
    if (v > tvs[b + 768]) {
        const float v0 = tvs[b], v1 = tvs[b + 256], v2 = tvs[b + 512];
        const int   i0 = tis[b], i1 = tis[b + 256], i2 = tis[b + 512];
        if (v > v2) {
            tvs[b + 768] = v2; tis[b + 768] = i2;
            if (v > v1) {
                tvs[b + 512] = v1; tis[b + 512] = i1;
                if (v > v0) {
                    tvs[b + 256] = v0; tis[b + 256] = i0;
                    tvs[b] = v; tis[b] = idx;
                } else { tvs[b + 256] = v; tis[b + 256] = idx; }
            } else { tvs[b + 512] = v; tis[b + 512] = idx; }
        } else { tvs[b + 768] = v; tis[b + 768] = idx; }
    }
}

// reg-side sorted-desc insert into 4-entry list
__device__ __forceinline__ void rins4(float* v4, int* i4, float v, int idx)
{
    if (v > v4[3]) {
        if (v > v4[2]) {
            v4[3] = v4[2]; i4[3] = i4[2];
            if (v > v4[1]) {
                v4[2] = v4[1]; i4[2] = i4[1];
                if (v > v4[0]) { v4[1] = v4[0]; i4[1] = i4[0]; v4[0] = v; i4[0] = idx; }
                else           { v4[1] = v; i4[1] = idx; }
            } else { v4[2] = v; i4[2] = idx; }
        } else { v4[3] = v; i4[3] = idx; }
    }
}

// ===========================================================================
// Kernel 2: bf16 mma.sync screen. 512 CTAs x 256 thr (8 warps, 2x4 tiling).
// A (128 rows x 512 c) resident in smem; B streamed in 64-wide k-chunks with
// register double-buffering; per-lane top-4 lists in smem; shuffle + smem
// merge down to per-row top-4 candidates.
// ===========================================================================
__global__ __launch_bounds__(256, 1) void vq_screen_kernel(const float* __restrict__ x)
{
    extern __shared__ __align__(16) char smem[];
    uint32_t* As32 = reinterpret_cast<uint32_t*>(smem + SM_AS);
    uint32_t* Bs32 = reinterpret_cast<uint32_t*>(smem + SM_BS);
    float*    tvs  = reinterpret_cast<float*>(smem + SM_TV);
    int*      tis  = reinterpret_cast<int*>(smem + SM_TI);

    const int tid  = threadIdx.x;
    const int lane = tid & 31;
    const int wid  = tid >> 5;
    const int wm   = wid >> 2;          // 0..1  (64 rows each)
    const int wn   = wid & 3;           // 0..3  (32 codes each)
    const int g    = lane >> 2;         // 0..7
    const int t4   = lane & 3;          // 0..3

    const int r0 = blockIdx.x * ROWS_PER_CTA;
    const int n  = r0 >> 11;
    const int t0 = r0 & (TD - 1);

    // ---- stage A: x[n, :, t0..t0+127] -> bf16 smem [row=t][k=c], padded ----
    {
        const int   t   = tid & 127;
        const int   cph = tid >> 7;                  // 0 or 1
        const float* xb = x + (size_t)n * CD * TD + t0 + t;
        for (int cp = cph; cp < 256; cp += 2) {      // cp = c/2
            const float v0 = __ldg(xb + (size_t)(2 * cp) * TD);
            const float v1 = __ldg(xb + (size_t)(2 * cp + 1) * TD);
            __nv_bfloat162 p = __floats2bfloat162_rn(v0, v1);
            As32[t * A_STRIDE_W + cp] = *reinterpret_cast<uint32_t*>(&p);
        }
    }
    // ---- init top-4 lists ----
#pragma unroll
    for (int s = 0; s < 32; ++s) {
        tvs[s * 256 + tid] = -INFINITY;
        tis[s * 256 + tid] = 0;
    }
    __syncthreads();

    // ---- main: 8 N-tiles of 128 codes ----
    uint4 pb[4];
    const int pb_code = tid >> 3;                    // 0..31 step handled below
    // B gmem load: idx = tid + i*256 -> code = idx>>3 (0..127), u = idx&7
    for (int ntile = 0; ntile < 8; ++ntile) {
        const int Nb = ntile * 128;

        float acc[4][4][4];
#pragma unroll
        for (int a = 0; a < 4; ++a)
#pragma unroll
            for (int b = 0; b < 4; ++b)
#pragma unroll
                for (int c = 0; c < 4; ++c) acc[a][b][c] = 0.0f;

        // preload chunk 0
#pragma unroll
        for (int i = 0; i < 4; ++i) {
            const int idx = tid + i * 256;
            const int code = idx >> 3, u = idx & 7;
            pb[i] = *reinterpret_cast<const uint4*>(
                g_cb_bf16 + (size_t)(Nb + code) * CD + u * 8);
        }

        for (int kc = 0; kc < 8; ++kc) {
            __syncthreads();                          // Bs consumers done
#pragma unroll
            for (int i = 0; i < 4; ++i) {
                const int idx = tid + i * 256;
                const int code = idx >> 3, u = idx & 7;
                *reinterpret_cast<uint4*>(&Bs32[code * B_STRIDE_W + u * 4]) = pb[i];
            }
            __syncthreads();                          // Bs ready
            if (kc < 7) {
#pragma unroll
                for (int i = 0; i < 4; ++i) {
                    const int idx = tid + i * 256;
                    const int code = idx >> 3, u = idx & 7;
                    pb[i] = *reinterpret_cast<const uint4*>(
                        g_cb_bf16 + (size_t)(Nb + code) * CD + (kc + 1) * 64 + u * 8);
                }
            }
            // 4 k16 steps over this 64-wide chunk
#pragma unroll
            for (int s = 0; s < 4; ++s) {
                uint32_t bf[4][2];
#pragma unroll
                for (int nt = 0; nt < 4; ++nt) {
                    const int cw = (wn * 32 + nt * 8 + g) * B_STRIDE_W + s * 8 + t4;
                    bf[nt][0] = Bs32[cw];
                    bf[nt][1] = Bs32[cw + 4];
                }
#pragma unroll
                for (int mt = 0; mt < 4; ++mt) {
                    const int rA = wm * 64 + mt * 16 + g;
                    const int aw = rA * A_STRIDE_W + kc * 32 + s * 8 + t4;
                    uint32_t af[4];
                    af[0] = As32[aw];
                    af[1] = As32[aw + 8 * A_STRIDE_W];
                    af[2] = As32[aw + 4];
                    af[3] = As32[aw + 8 * A_STRIDE_W + 4];
#pragma unroll
                    for (int nt = 0; nt < 4; ++nt)
                        mma16816(acc[mt][nt], af, bf[nt]);
                }
            }
        }

        // fold this N-tile into per-lane smem top-4 lists
#pragma unroll
        for (int nt = 0; nt < 4; ++nt) {
            const int c2 = Nb + wn * 32 + nt * 8 + 2 * t4;
            const float h0 = __ldg(&g_half_hat[c2]);
            const float h1 = __ldg(&g_half_hat[c2 + 1]);
#pragma unroll
            for (int mt = 0; mt < 4; ++mt) {
                ins4(tvs, tis, tid, mt * 2,     acc[mt][nt][0] - h0, c2);
                ins4(tvs, tis, tid, mt * 2,     acc[mt][nt][1] - h1, c2 + 1);
                ins4(tvs, tis, tid, mt * 2 + 1, acc[mt][nt][2] - h0, c2);
                ins4(tvs, tis, tid, mt * 2 + 1, acc[mt][nt][3] - h1, c2 + 1);
            }
        }
    }

    __syncthreads();     // all warps done with Bs; reuse it as merge scratch
    float* mv = reinterpret_cast<float*>(smem + SM_MV);   // [row][wn][4]
    int*   mi = reinterpret_cast<int*>(smem + SM_MI);

    // quad merge (lanes t4=0..3 share rows) then one lane writes per slot
#pragma unroll
    for (int slot = 0; slot < 8; ++slot) {
        float v4[4]; int i4[4];
#pragma unroll
        for (int j = 0; j < 4; ++j) {
            v4[j] = tvs[(slot * 4 + j) * 256 + tid];
            i4[j] = tis[(slot * 4 + j) * 256 + tid];
        }
#pragma unroll
        for (int off = 1; off <= 2; off <<= 1) {
            float ov[4]; int oi[4];
#pragma unroll
            for (int j = 0; j < 4; ++j) {
                ov[j] = __shfl_xor_sync(0xffffffffu, v4[j], off);
                oi[j] = __shfl_xor_sync(0xffffffffu, i4[j], off);
            }
#pragma unroll
            for (int j = 0; j < 4; ++j) rins4(v4, i4, ov[j], oi[j]);
        }
        if (t4 == 0) {
            const int row = wm * 64 + (slot >> 1) * 16 + g + (slot & 1) * 8;
            const int e = (row * 4 + wn) * 4;
#pragma unroll
            for (int j = 0; j < 4; ++j) { mv[e + j] = v4[j]; mi[e + j] = i4[j]; }
        }
    }
    __syncthreads();

    // final per-row merge of the 4 warp_n lists
    if (tid < 128) {
        float v4[4] = { -INFINITY, -INFINITY, -INFINITY, -INFINITY };
        int   i4[4] = { 0, 0, 0, 0 };
#pragma unroll
        for (int e = 0; e < 16; ++e)
            rins4(v4, i4, mv[tid * 16 + e], mi[tid * 16 + e]);
        const size_t r = (size_t)(r0 + tid);
        *reinterpret_cast<float4*>(&g_scr_v[r * 4]) = make_float4(v4[0], v4[1], v4[2], v4[3]);
        *reinterpret_cast<int4*>(&g_scr_i[r * 4])   = make_int4(i4[0], i4[1], i4[2], i4[3]);
    }
}

// ===========================================================================
// Kernel 3: exact fp32 rescore of screen candidates within margin, then
// gather-write winning codebook row back into [N, C, T].
// ===========================================================================
__global__ __launch_bounds__(128) void vq_rescore_gather_kernel(
    const float* __restrict__ x, const float* __restrict__ cb,
    float* __restrict__ out, long long out_size)
{
    const int r = blockIdx.x * 128 + threadIdx.x;
    const int n = r >> 11;
    const int t = r & (TD - 1);

    const float4 sv = *reinterpret_cast<const float4*>(&g_scr_v[(size_t)r * 4]);
    const int4   si = *reinterpret_cast<const int4*>(&g_scr_i[(size_t)r * 4]);
    const float thr = sv.x - 1.0f;     // margin ~8 sigma of bf16 screen noise

    const float* xp = x + (size_t)n * CD * TD + t;

    float best;
    {
        const float* c0 = cb + (size_t)si.x * CD;
        float a = 0.0f;
#pragma unroll 8
        for (int c = 0; c < CD; ++c)
            a = fmaf(__ldg(xp + (size_t)c * TD), __ldg(c0 + c), a);
        best = a - __ldg(&g_half_exact[si.x]);
    }
    int bidx = si.x;

    const int   cid[3] = { si.y, si.z, si.w };
    const float cvv[3] = { sv.y, sv.z, sv.w };
#pragma unroll
    for (int m = 0; m < 3; ++m) {
        if (cvv[m] >= thr) {
            const float* cm = cb + (size_t)cid[m] * CD;
            float a = 0.0f;
#pragma unroll 8
            for (int c = 0; c < CD; ++c)
                a = fmaf(__ldg(xp + (size_t)c * TD), __ldg(cm + c), a);
            const float s = a - __ldg(&g_half_exact[cid[m]]);
            if (s > best || (s == best && cid[m] < bidx)) { best = s; bidx = cid[m]; }
        }
    }

    const float4* crow = reinterpret_cast<const float4*>(cb + (size_t)bidx * CD);
    float* ob = out + (size_t)n * CD * TD + t;
#pragma unroll 4
    for (int c4 = 0; c4 < CD / 4; ++c4) {
        const float4 w = __ldg(crow + c4);
        ob[(size_t)(c4 * 4 + 0) * TD] = w.x;
        ob[(size_t)(c4 * 4 + 1) * TD] = w.y;
        ob[(size_t)(c4 * 4 + 2) * TD] = w.z;
        ob[(size_t)(c4 * 4 + 3) * TD] = w.w;
    }
    if (r == 0) {
        for (long long e = XD_ELEMS; e < out_size; ++e) out[e] = 0.0f;
    }
}

// ===========================================================================
extern "C" void kernel_launch(void* const* d_in, const int* in_sizes, int n_in,
                              void* d_out, int out_size)
{
    const float* x  = (const float*)d_in[0];
    const float* cb = (const float*)d_in[1];
    if (n_in >= 2 && in_sizes[0] < in_sizes[1]) {
        const float* tmp = x; x = cb; cb = tmp;
    }
    float* out = (float*)d_out;

    cudaFuncSetAttribute(vq_screen_kernel,
                         cudaFuncAttributeMaxDynamicSharedMemorySize, SM_TOTAL);

    vq_prep_kernel<<<KC, 128>>>(cb);
    vq_screen_kernel<<<N_SCREEN_CTAS, 256, SM_TOTAL>>>(x);
    vq_rescore_gather_kernel<<<NT_ROWS / 128, 128>>>(x, cb, out, (long long)out_size);
}